// round 10
// baseline (speedup 1.0000x reference)
#include <cuda_runtime.h>

#define NN 4096

typedef unsigned long long ull;

__device__ __forceinline__ ull pack2(float lo, float hi) {
    ull r; asm("mov.b64 %0, {%1, %2};" : "=l"(r) : "f"(lo), "f"(hi)); return r;
}
__device__ __forceinline__ void unpack2(ull v, float &lo, float &hi) {
    asm("mov.b64 {%0, %1}, %2;" : "=f"(lo), "=f"(hi) : "l"(v));
}
__device__ __forceinline__ void ffma2(ull &d, ull a, ull b) {
    asm("fma.rn.f32x2 %0, %1, %2, %0;" : "+l"(d) : "l"(a), "l"(b));
}

// ---------------- scratch ----------------
__device__ float g_feats[8 * 80 * NN];      // [b][0:8]=featB [8:16]=featC [16:80]=featD
__device__ float g_x1[8 * 64 * NN];         // after PAM
__device__ float g_x2[8 * 64 * NN];         // after CAM
__device__ float g_gramP[8 * 16 * 64 * 64]; // partial grams
__device__ float g_attG[8 * 64 * 64];       // CAM attention
__device__ float g_conv[8 * 128 * NN];      // conv3x3 output
__device__ float g_mean[128];
__device__ float g_rstd[128];

// ---------------- K1: fused 1x1 convs -> featB/featC/featD (FFMA2) --------
__global__ void __launch_bounds__(256) k1_conv1x1(
    const float* __restrict__ x,
    const float* __restrict__ wb, const float* __restrict__ bbv,
    const float* __restrict__ wc, const float* __restrict__ bcv,
    const float* __restrict__ wd, const float* __restrict__ bdv)
{
    __shared__ __align__(16) float ws[80 * 64];
    __shared__ float bs[80];
    const int t = threadIdx.x;
    const int b = blockIdx.y;
    const int n = blockIdx.x * 256 + t;

    for (int idx = t; idx < 80 * 64; idx += 256) {
        int row = idx >> 6;
        float v;
        if (row < 8)       v = wb[idx];
        else if (row < 16) v = wc[idx - 512];
        else               v = wd[idx - 1024];
        ws[idx] = v;
    }
    if (t < 80) bs[t] = (t < 8) ? bbv[t] : (t < 16 ? bcv[t - 8] : bdv[t - 16]);
    __syncthreads();

    ull xr2[32];
    const float* xb = x + b * 64 * NN + n;
    #pragma unroll
    for (int c2 = 0; c2 < 32; c2++)
        xr2[c2] = pack2(xb[(2 * c2) * NN], xb[(2 * c2 + 1) * NN]);

    float* dst = g_feats + b * 80 * NN + n;
    for (int o = 0; o < 80; o++) {
        ull a2 = 0ull;
        const ulonglong2* w2 = (const ulonglong2*)(ws + o * 64);
        #pragma unroll
        for (int c4 = 0; c4 < 16; c4++) {
            ulonglong2 wv = w2[c4];
            ffma2(a2, wv.x, xr2[2 * c4]);
            ffma2(a2, wv.y, xr2[2 * c4 + 1]);
        }
        float lo, hi; unpack2(a2, lo, hi);
        dst[o * NN] = lo + hi + bs[o];
    }
}

// ---------------- K2: PAM flash attention (fp32, FFMA2 S + AV) -------------
// 128 q per block, keys in tiles of 32. S phase: thread = (q, m-half),
// m processed in pairs via FFMA2 with K staged as packed m-pairs (uniform
// broadcast LDS.64). AV phase: R3-proven layout (cg=warp 8c, qg=lane 4q).
__global__ void __launch_bounds__(256, 3) k2_flash(const float* __restrict__ x,
                                                   const float* __restrict__ alpha)
{
    __shared__ ull Ks2[8][17];                    // K m-pairs
    __shared__ __align__(16) float Vt[32 * 68];   // V^T [m][c]
    __shared__ __align__(16) float Pt[32 * 132];  // P [m][q]
    __shared__ float Ls[256];
    __shared__ float Lq[128];

    const int t = threadIdx.x;
    const int b = blockIdx.y;
    const int q0 = blockIdx.x * 128;
    const float* fB = g_feats + b * 80 * NN;
    const float* fC = fB + 8 * NN;
    const float* fD = fB + 16 * NN;

    const int qS = t & 127;
    const int mh = (t >> 7) * 16;      // this thread's m-half base
    ull qd[8];
    #pragma unroll
    for (int k = 0; k < 8; k++) {
        float qv = fB[k * NN + q0 + qS];
        qd[k] = pack2(qv, qv);
    }

    const int cg = t >> 5;
    const int qg = t & 31;

    ull acc2[4][4];
    #pragma unroll
    for (int i = 0; i < 4; i++)
        #pragma unroll
        for (int j = 0; j < 4; j++) acc2[i][j] = 0ull;
    float lacc = 0.f;

    for (int kt = 0; kt < 128; kt++) {
        const int m0 = kt * 32;
        __syncthreads();               // prev AV done reading Pt/Vt/Ks2
        // stage K as m-pairs (threads 0..127)
        if (t < 128) {
            float2 kv = *(const float2*)(fC + (t >> 4) * NN + m0 + 2 * (t & 15));
            Ks2[t >> 4][t & 15] = pack2(kv.x, kv.y);
        }
        // stage V transposed
        #pragma unroll
        for (int rep = 0; rep < 8; rep++) {
            int idx = t + rep * 256;
            int c = idx >> 5, m = idx & 31;
            Vt[m * 68 + c] = fD[c * NN + m0 + m];
        }
        __syncthreads();
        // S phase: 8 m-pairs per thread, FFMA2
        #pragma unroll
        for (int mp = 0; mp < 8; mp++) {
            int m = mh + 2 * mp;
            ull s2 = 0ull;
            #pragma unroll
            for (int k = 0; k < 8; k++)
                ffma2(s2, qd[k], Ks2[k][(m >> 1)]);
            float s0, s1; unpack2(s2, s0, s1);
            float p0 = __expf(s0), p1 = __expf(s1);
            lacc += p0 + p1;
            Pt[m * 132 + qS]       = p0;
            Pt[(m + 1) * 132 + qS] = p1;
        }
        __syncthreads();
        // AV phase: acc[c][q] += V[m][c] * P[m][q], packed along c
        #pragma unroll 4
        for (int m = 0; m < 32; m++) {
            const ulonglong2* vr = (const ulonglong2*)(Vt + m * 68 + 8 * cg);
            ulonglong2 va = vr[0], vb = vr[1];
            float4 p4 = *(const float4*)(Pt + m * 132 + 4 * qg);
            ull pd0 = pack2(p4.x, p4.x);
            ull pd1 = pack2(p4.y, p4.y);
            ull pd2 = pack2(p4.z, p4.z);
            ull pd3 = pack2(p4.w, p4.w);
            ffma2(acc2[0][0], va.x, pd0); ffma2(acc2[1][0], va.y, pd0);
            ffma2(acc2[2][0], vb.x, pd0); ffma2(acc2[3][0], vb.y, pd0);
            ffma2(acc2[0][1], va.x, pd1); ffma2(acc2[1][1], va.y, pd1);
            ffma2(acc2[2][1], vb.x, pd1); ffma2(acc2[3][1], vb.y, pd1);
            ffma2(acc2[0][2], va.x, pd2); ffma2(acc2[1][2], va.y, pd2);
            ffma2(acc2[2][2], vb.x, pd2); ffma2(acc2[3][2], vb.y, pd2);
            ffma2(acc2[0][3], va.x, pd3); ffma2(acc2[1][3], va.y, pd3);
            ffma2(acc2[2][3], vb.x, pd3); ffma2(acc2[3][3], vb.y, pd3);
        }
    }
    __syncthreads();
    Ls[t] = lacc;
    __syncthreads();
    if (t < 128) Lq[t] = __ldg(alpha) / (Ls[t] + Ls[t + 128]);
    __syncthreads();

    float* x1 = g_x1 + b * 64 * NN;
    const float* xb = x + b * 64 * NN;
    #pragma unroll
    for (int i2 = 0; i2 < 4; i2++) {
        int c0 = 8 * cg + 2 * i2;
        #pragma unroll
        for (int j = 0; j < 4; j++) {
            int n = q0 + 4 * qg + j;
            float lo, hi; unpack2(acc2[i2][j], lo, hi);
            float sc = Lq[4 * qg + j];
            x1[c0 * NN + n]       = lo * sc + xb[c0 * NN + n];
            x1[(c0 + 1) * NN + n] = hi * sc + xb[(c0 + 1) * NN + n];
        }
    }
}

// ---------------- K3: CAM gram partials (16 n-chunks) ----------------------
__global__ void __launch_bounds__(256) k3_gram()
{
    __shared__ float Xs[64 * 65];
    const int b = blockIdx.y, ch = blockIdx.x;
    const int t = threadIdx.x;
    const int cg = t >> 4, dg = t & 15;
    float acc[4][4];
    #pragma unroll
    for (int i = 0; i < 4; i++)
        #pragma unroll
        for (int j = 0; j < 4; j++) acc[i][j] = 0.f;

    const float* xb = g_x1 + b * 64 * NN + ch * 256;
    for (int sub = 0; sub < 4; sub++) {
        __syncthreads();
        #pragma unroll
        for (int rep = 0; rep < 16; rep++) {
            int idx = t + rep * 256;
            int c = idx >> 6, n = idx & 63;
            Xs[c * 65 + n] = xb[c * NN + sub * 64 + n];
        }
        __syncthreads();
        for (int n = 0; n < 64; n++) {
            float cv[4], dv[4];
            #pragma unroll
            for (int i = 0; i < 4; i++) cv[i] = Xs[(4 * cg + i) * 65 + n];
            #pragma unroll
            for (int j = 0; j < 4; j++) dv[j] = Xs[(4 * dg + j) * 65 + n];
            #pragma unroll
            for (int i = 0; i < 4; i++)
                #pragma unroll
                for (int j = 0; j < 4; j++) acc[i][j] += cv[i] * dv[j];
        }
    }
    float* dst = g_gramP + (b * 16 + ch) * 4096;
    #pragma unroll
    for (int i = 0; i < 4; i++)
        #pragma unroll
        for (int j = 0; j < 4; j++)
            dst[(4 * cg + i) * 64 + 4 * dg + j] = acc[i][j];
}

// ---------------- K3b: reduce partials + row softmax(-att), 64 blocks ------
__global__ void __launch_bounds__(256) k3b_soft()
{
    __shared__ float A[512];
    const int b = blockIdx.x, rg = blockIdx.y;   // 8 rows per block
    const int t = threadIdx.x;
    const float* src = g_gramP + b * 16 * 4096 + rg * 512;
    #pragma unroll
    for (int e = t; e < 512; e += 256) {
        float s = 0.f;
        #pragma unroll
        for (int ch = 0; ch < 16; ch++) s += src[ch * 4096 + e];
        A[e] = s;
    }
    __syncthreads();
    const int w = t >> 5, l = t & 31;
    float v0 = A[w * 64 + l], v1 = A[w * 64 + 32 + l];
    float mn = fminf(v0, v1);
    #pragma unroll
    for (int o = 16; o; o >>= 1) mn = fminf(mn, __shfl_xor_sync(0xffffffffu, mn, o));
    float e0 = __expf(mn - v0), e1 = __expf(mn - v1);
    float s = e0 + e1;
    #pragma unroll
    for (int o = 16; o; o >>= 1) s += __shfl_xor_sync(0xffffffffu, s, o);
    float inv = 1.f / s;
    float* dst = g_attG + b * 4096 + (rg * 8 + w) * 64;
    dst[l]      = e0 * inv;
    dst[32 + l] = e1 * inv;
}

// ---------------- K4: fe = att @ x1 ; x2 = beta*fe + x1 (FFMA2) ------------
__global__ void __launch_bounds__(256) k4_cam(const float* __restrict__ beta)
{
    __shared__ __align__(16) float A[4096];
    const int b = blockIdx.y;
    const int t = threadIdx.x;
    const int n = blockIdx.x * 256 + t;
    const float* src = g_attG + b * 4096;
    #pragma unroll
    for (int rep = 0; rep < 16; rep++) A[t + rep * 256] = src[t + rep * 256];
    __syncthreads();
    const float* x1 = g_x1 + b * 64 * NN;
    float xr[64];
    ull xr2[32];
    #pragma unroll
    for (int d = 0; d < 64; d++) xr[d] = x1[d * NN + n];
    #pragma unroll
    for (int d2 = 0; d2 < 32; d2++) xr2[d2] = pack2(xr[2 * d2], xr[2 * d2 + 1]);
    const float bt = __ldg(beta);
    float* x2 = g_x2 + b * 64 * NN;
    #pragma unroll 2
    for (int c = 0; c < 64; c++) {
        ull a2 = 0ull;
        const ulonglong2* ar = (const ulonglong2*)(A + c * 64);
        #pragma unroll
        for (int d4 = 0; d4 < 16; d4++) {
            ulonglong2 av = ar[d4];
            ffma2(a2, av.x, xr2[2 * d4]);
            ffma2(a2, av.y, xr2[2 * d4 + 1]);
        }
        float lo, hi; unpack2(a2, lo, hi);
        x2[c * NN + n] = bt * (lo + hi) + xr[c];
    }
}

// ---------------- K5: conv3x3 (bias skipped: cancels through BN) -----------
__global__ void __launch_bounds__(256) k5_conv(const float* __restrict__ cw)
{
    __shared__ __align__(16) float ins[16 * 324];  // [ic16][18][18]
    __shared__ ull ws2[16 * 16 * 9];               // [oc2(16)][ic(16)][9] oc-paired
    const int t = threadIdx.x;
    const int b = blockIdx.z;
    const int ocg = blockIdx.y;                    // oc base = ocg*32
    const int tile = blockIdx.x;
    const int th0 = (tile >> 2) * 16, tw0 = (tile & 3) * 16;
    const int og = t >> 6;                         // 0..3
    const int quad = t & 63;
    const int qr = quad >> 3, qc = quad & 7;
    const int r0 = 2 * qr, c0 = 2 * qc;

    const float* xb = g_x2 + b * 64 * NN;
    ull acc2[4][4];
    #pragma unroll
    for (int i = 0; i < 4; i++)
        #pragma unroll
        for (int j = 0; j < 4; j++) acc2[i][j] = 0ull;

    for (int cic = 0; cic < 4; cic++) {
        __syncthreads();
        for (int idx = t; idx < 16 * 324; idx += 256) {
            int ic = idx / 324, rem = idx % 324;
            int r = rem / 18, cc = rem % 18;
            int h = th0 + r - 1, w = tw0 + cc - 1;
            float v = 0.f;
            if ((unsigned)h < 64u && (unsigned)w < 64u)
                v = xb[(cic * 16 + ic) * NN + h * 64 + w];
            ins[idx] = v;
        }
        for (int idx = t; idx < 2304; idx += 256) {
            int oc2 = idx / 144, rem = idx % 144;
            int ic = rem / 9, kk = rem % 9;
            int oce = ocg * 32 + 2 * oc2;
            const float* wp = cw + (oce * 64 + cic * 16 + ic) * 9 + kk;
            ws2[idx] = pack2(wp[0], wp[64 * 9]);
        }
        __syncthreads();
        for (int ic = 0; ic < 16; ic++) {
            ull pvd[4][4];
            #pragma unroll
            for (int dr = 0; dr < 4; dr++)
                #pragma unroll
                for (int dc = 0; dc < 4; dc++) {
                    float v = ins[ic * 324 + (r0 + dr) * 18 + (c0 + dc)];
                    pvd[dr][dc] = pack2(v, v);
                }
            #pragma unroll
            for (int o2 = 0; o2 < 4; o2++) {
                const ull* wr = ws2 + ((og * 4 + o2) * 16 + ic) * 9;
                #pragma unroll
                for (int kh = 0; kh < 3; kh++)
                    #pragma unroll
                    for (int kw = 0; kw < 3; kw++) {
                        ull wv = wr[3 * kh + kw];
                        ffma2(acc2[o2][0], wv, pvd[kh][kw]);
                        ffma2(acc2[o2][1], wv, pvd[kh][kw + 1]);
                        ffma2(acc2[o2][2], wv, pvd[kh + 1][kw]);
                        ffma2(acc2[o2][3], wv, pvd[kh + 1][kw + 1]);
                    }
            }
        }
    }
    #pragma unroll
    for (int o2 = 0; o2 < 4; o2++) {
        int oce = ocg * 32 + (og * 4 + o2) * 2;
        #pragma unroll
        for (int pix = 0; pix < 4; pix++) {
            int ph = pix >> 1, pw = pix & 1;
            int h = th0 + r0 + ph, w = tw0 + c0 + pw;
            float lo, hi; unpack2(acc2[o2][pix], lo, hi);
            g_conv[(b * 128 + oce) * NN + h * 64 + w]       = lo;
            g_conv[(b * 128 + oce + 1) * NN + h * 64 + w]   = hi;
        }
    }
}

// ---------------- K6: BN batch stats per channel ---------------------------
__global__ void __launch_bounds__(256) k6_stats()
{
    __shared__ float rs[256], rs2[256];
    const int oc = blockIdx.x, t = threadIdx.x;
    float s = 0.f, s2 = 0.f;
    for (int idx = t; idx < 32768; idx += 256) {
        int bb = idx >> 12, n = idx & 4095;
        float v = g_conv[(bb * 128 + oc) * NN + n];
        s += v; s2 += v * v;
    }
    rs[t] = s; rs2[t] = s2;
    __syncthreads();
    for (int o = 128; o; o >>= 1) {
        if (t < o) { rs[t] += rs[t + o]; rs2[t] += rs2[t + o]; }
        __syncthreads();
    }
    if (t == 0) {
        float mean = rs[0] * (1.f / 32768.f);
        float var  = rs2[0] * (1.f / 32768.f) - mean * mean;
        g_mean[oc] = mean;
        g_rstd[oc] = rsqrtf(var + 1e-5f);
    }
}

// ---------------- K7: normalize + ReLU + maxpool(2,2,hpad) -----------------
__global__ void __launch_bounds__(256) k7_pool(const float* __restrict__ gamma,
                                              const float* __restrict__ bbeta,
                                              float* __restrict__ out)
{
    const int p = blockIdx.x;          // b*128 + oc
    const int oc = p & 127;
    const float a  = g_rstd[oc] * __ldg(gamma + oc);
    const float bc = __ldg(bbeta + oc) - g_mean[oc] * a;
    const float* cp = g_conv + p * NN;
    float* op = out + p * 33 * 32;
    for (int idx = threadIdx.x; idx < 1056; idx += 256) {
        int oh = idx >> 5, ow = idx & 31;
        int r0 = 2 * oh - 1, r1 = 2 * oh;
        int c0 = 2 * ow;
        float m = 0.f;  // ReLU floor; -inf pad rows excluded
        if (r0 >= 0) {
            m = fmaxf(m, cp[r0 * 64 + c0] * a + bc);
            m = fmaxf(m, cp[r0 * 64 + c0 + 1] * a + bc);
        }
        if (r1 < 64) {
            m = fmaxf(m, cp[r1 * 64 + c0] * a + bc);
            m = fmaxf(m, cp[r1 * 64 + c0 + 1] * a + bc);
        }
        op[idx] = m;
    }
}

extern "C" void kernel_launch(void* const* d_in, const int* in_sizes, int n_in,
                              void* d_out, int out_size)
{
    const float* x   = (const float*)d_in[0];
    const float* wb  = (const float*)d_in[1];
    const float* bb  = (const float*)d_in[2];
    const float* wc  = (const float*)d_in[3];
    const float* bc  = (const float*)d_in[4];
    const float* wd  = (const float*)d_in[5];
    const float* bd  = (const float*)d_in[6];
    const float* al  = (const float*)d_in[7];
    const float* be  = (const float*)d_in[8];
    const float* cw  = (const float*)d_in[9];
    const float* gam = (const float*)d_in[11];
    const float* bet = (const float*)d_in[12];
    float* out = (float*)d_out;

    k1_conv1x1<<<dim3(16, 8), 256>>>(x, wb, bb, wc, bc, wd, bd);
    k2_flash<<<dim3(32, 8), 256>>>(x, al);
    k3_gram<<<dim3(16, 8), 256>>>();
    k3b_soft<<<dim3(8, 8), 256>>>();
    k4_cam<<<dim3(16, 8), 256>>>(be);
    k5_conv<<<dim3(16, 4, 8), 256>>>(cw);
    k6_stats<<<128, 256>>>();
    k7_pool<<<1024, 256>>>(gam, bet, out);
}